// round 2
// baseline (speedup 1.0000x reference)
#include <cuda_runtime.h>
#include <math.h>

// Problem constants (fixed by the reference)
#define BB 256
#define TT 200
#define QQ 1000
#define TM1 199   // T - 1

// Scratch: per-student loss (device global — no allocations allowed)
__device__ float g_student_loss[BB];

// One block per student. Thread i (< 199) handles step i.
__global__ void __launch_bounds__(256)
student_kernel(const float* __restrict__ logit_c,
               const float* __restrict__ logit_t,
               const int*   __restrict__ q_idx,
               const int*   __restrict__ correct,
               float*       __restrict__ out)
{
    __shared__ float sh[256];
    __shared__ int   shi[256];

    const int s = blockIdx.x;
    const int i = threadIdx.x;
    const bool act = (i < TM1);

    float* __restrict__ p_mean = out + 1;
    float* __restrict__ gt     = out + 1 + (size_t)BB * TM1;

    float pc = 0.0f, pt = 0.0f, a = 0.0f;
    if (act) {
        const int base = s * TT + i;            // (s, i)
        const int q    = q_idx[base + 1];       // q_idx[s, i+1]
        a = (float)correct[base + 1];           // correct[s, i+1]
        const size_t row = (size_t)base * QQ;
        const float lc = logit_c[row + q];
        const float lt = logit_t[row + q];
        pc = 1.0f / (1.0f + expf(-lc));
        pt = 1.0f / (1.0f + expf(-lt));
        const size_t o = (size_t)s * TM1 + i;
        p_mean[o] = 0.5f * (pt + pc);
        gt[o]     = a;
    }

    // last = max index with pc > 0  (dynamic trim)
    shi[i] = (act && pc > 0.0f) ? i : -1;
    __syncthreads();
    #pragma unroll
    for (int off = 128; off > 0; off >>= 1) {
        if (i < off) shi[i] = max(shi[i], shi[i + off]);
        __syncthreads();
    }
    const int last = shi[0];
    __syncthreads();

    // masked BCE(pt) + BCE(pc)
    float e = 0.0f;
    if (act && i <= last) {
        const float lpt  = fmaxf(logf(pt),    -100.0f);
        const float l1pt = fmaxf(log1pf(-pt), -100.0f);
        const float lpc  = fmaxf(logf(pc),    -100.0f);
        const float l1pc = fmaxf(log1pf(-pc), -100.0f);
        e = -(a * lpt + (1.0f - a) * l1pt)
          - (a * lpc + (1.0f - a) * l1pc);
    }
    sh[i] = e;
    __syncthreads();
    #pragma unroll
    for (int off = 128; off > 0; off >>= 1) {
        if (i < off) sh[i] += sh[i + off];
        __syncthreads();
    }
    if (i == 0) {
        const float cnt = (float)(last + 1);
        g_student_loss[s] = sh[0] / cnt;
    }
}

// Deterministic final sum of the 256 per-student losses.
__global__ void __launch_bounds__(256)
finalize_kernel(float* __restrict__ out)
{
    __shared__ float sh[256];
    const int i = threadIdx.x;
    sh[i] = g_student_loss[i];
    __syncthreads();
    #pragma unroll
    for (int off = 128; off > 0; off >>= 1) {
        if (i < off) sh[i] += sh[i + off];
        __syncthreads();
    }
    if (i == 0) out[0] = sh[0];
}

extern "C" void kernel_launch(void* const* d_in, const int* in_sizes, int n_in,
                              void* d_out, int out_size)
{
    const float* logit_c = (const float*)d_in[0];
    const float* logit_t = (const float*)d_in[1];
    const int*   q_idx   = (const int*)d_in[2];
    const int*   correct = (const int*)d_in[3];
    float* out = (float*)d_out;

    student_kernel<<<BB, 256>>>(logit_c, logit_t, q_idx, correct, out);
    finalize_kernel<<<1, 256>>>(out);
}

// round 3
// speedup vs baseline: 1.0257x; 1.0257x over previous
#include <cuda_runtime.h>
#include <math.h>

// Problem constants (fixed by the reference)
#define BB 256
#define TT 200
#define QQ 1000
#define TM1 199   // T - 1

// Scratch (no allocations allowed): per-student loss + completion counter
__device__ float g_student_loss[BB];
__device__ unsigned int g_done_count = 0;   // reset by last block each run

// One block per student; thread i (< 199) handles step i.
// Last block to finish performs the deterministic final sum into out[0].
__global__ void __launch_bounds__(256)
fused_kernel(const float* __restrict__ logit_c,
             const float* __restrict__ logit_t,
             const int*   __restrict__ q_idx,
             const int*   __restrict__ correct,
             float*       __restrict__ out)
{
    __shared__ float shf[8];
    __shared__ int   shi[8];
    __shared__ int   sh_last;
    __shared__ bool  sh_is_last_block;

    const int s    = blockIdx.x;
    const int i    = threadIdx.x;
    const int lane = i & 31;
    const int warp = i >> 5;
    const bool act = (i < TM1);

    float* __restrict__ p_mean = out + 1;
    float* __restrict__ gt     = out + 1 + (size_t)BB * TM1;

    float pc = 0.0f, pt = 0.0f, a = 0.0f;
    if (act) {
        const int base = s * TT + i;            // (s, i)
        const int q    = q_idx[base + 1];       // q_idx[s, i+1]
        a = (float)correct[base + 1];           // correct[s, i+1]
        const size_t row = (size_t)base * QQ;
        const float lc = logit_c[row + q];
        const float lt = logit_t[row + q];
        pc = 1.0f / (1.0f + expf(-lc));
        pt = 1.0f / (1.0f + expf(-lt));
        const size_t o = (size_t)s * TM1 + i;
        p_mean[o] = 0.5f * (pt + pc);
        gt[o]     = a;
    }

    // ---- last = max index with pc > 0 (dynamic trim), warp-shuffle reduce ----
    int idx = (act && pc > 0.0f) ? i : -1;
    #pragma unroll
    for (int off = 16; off > 0; off >>= 1)
        idx = max(idx, __shfl_xor_sync(0xFFFFFFFFu, idx, off));
    if (lane == 0) shi[warp] = idx;
    __syncthreads();
    if (warp == 0) {
        int v = shi[lane & 7];
        #pragma unroll
        for (int off = 4; off > 0; off >>= 1)
            v = max(v, __shfl_xor_sync(0xFFFFFFFFu, v, off));
        if (lane == 0) sh_last = v;
    }
    __syncthreads();
    const int last = sh_last;

    // ---- masked BCE(pt) + BCE(pc), warp-shuffle sum ----
    float e = 0.0f;
    if (act && i <= last) {
        const float lpt  = fmaxf(logf(pt),    -100.0f);
        const float l1pt = fmaxf(log1pf(-pt), -100.0f);
        const float lpc  = fmaxf(logf(pc),    -100.0f);
        const float l1pc = fmaxf(log1pf(-pc), -100.0f);
        e = -(a * lpt + (1.0f - a) * l1pt)
          - (a * lpc + (1.0f - a) * l1pc);
    }
    #pragma unroll
    for (int off = 16; off > 0; off >>= 1)
        e += __shfl_xor_sync(0xFFFFFFFFu, e, off);
    if (lane == 0) shf[warp] = e;
    __syncthreads();
    if (i == 0) {
        float sum = 0.0f;
        #pragma unroll
        for (int w = 0; w < 8; w++) sum += shf[w];
        g_student_loss[s] = sum / (float)(last + 1);

        // publish, then take a ticket
        __threadfence();
        unsigned int ticket = atomicAdd(&g_done_count, 1u);
        sh_is_last_block = (ticket == BB - 1);
    }
    __syncthreads();

    // ---- last block standing: deterministic final sum of 256 losses ----
    if (sh_is_last_block) {
        __threadfence();                      // acquire other blocks' writes
        float v = g_student_loss[i];          // 256 threads, 256 values
        #pragma unroll
        for (int off = 16; off > 0; off >>= 1)
            v += __shfl_xor_sync(0xFFFFFFFFu, v, off);
        if (lane == 0) shf[warp] = v;
        __syncthreads();
        if (i == 0) {
            float sum = 0.0f;
            #pragma unroll
            for (int w = 0; w < 8; w++) sum += shf[w];
            out[0] = sum;
            g_done_count = 0;                 // reset for next graph replay
        }
    }
}

extern "C" void kernel_launch(void* const* d_in, const int* in_sizes, int n_in,
                              void* d_out, int out_size)
{
    const float* logit_c = (const float*)d_in[0];
    const float* logit_t = (const float*)d_in[1];
    const int*   q_idx   = (const int*)d_in[2];
    const int*   correct = (const int*)d_in[3];
    float* out = (float*)d_out;

    fused_kernel<<<BB, 256>>>(logit_c, logit_t, q_idx, correct, out);
}

// round 4
// speedup vs baseline: 1.0295x; 1.0037x over previous
#include <cuda_runtime.h>
#include <math.h>

// Problem constants (fixed by the reference)
#define BB 256
#define TT 200
#define QQ 1000
#define TM1 199   // T - 1
#define NTHR 224  // 7 warps, covers 199 active lanes
#define NWARP 7
#define FXSCALE 17592186044416.0   // 2^44 fixed-point scale

// Scratch (no allocations allowed)
__device__ unsigned long long g_acc  = 0ull;  // fixed-point sum of per-student losses
__device__ unsigned int       g_done = 0u;    // completion tickets

__global__ void __launch_bounds__(NTHR)
fused_kernel(const float* __restrict__ logit_c,
             const float* __restrict__ logit_t,
             const int*   __restrict__ q_idx,
             const int*   __restrict__ correct,
             float*       __restrict__ out)
{
    __shared__ float shf[NWARP];
    __shared__ float sh_e[NTHR];    // fallback only
    __shared__ float sh_pc[NTHR];   // fallback only
    __shared__ float sh_res[2];     // {esum, cnt}

    const int s    = blockIdx.x;
    const int i    = threadIdx.x;
    const int lane = i & 31;
    const int warp = i >> 5;
    const bool act = (i < TM1);

    float* __restrict__ p_mean = out + 1;
    float* __restrict__ gt     = out + 1 + (size_t)BB * TM1;

    float pc = 0.0f, e = 0.0f;
    if (act) {
        const int base = s * TT + i;            // (s, i)
        const int q    = q_idx[base + 1];       // q_idx[s, i+1]
        const float a  = (float)correct[base + 1];
        const size_t row = (size_t)base * QQ;
        const float xc = logit_c[row + q];
        const float xt = logit_t[row + q];
        const float ec = __expf(-xc);           // e^{-xc}
        const float et = __expf(-xt);           // e^{-xt}
        pc = __fdividef(1.0f, 1.0f + ec);
        const float pt = __fdividef(1.0f, 1.0f + et);
        const size_t o = (size_t)s * TM1 + i;
        p_mean[o] = 0.5f * (pt + pc);
        gt[o]     = a;
        // BCE(p,a) with p=sigmoid(x):  -[a log p + (1-a) log(1-p)]
        //   = (1-a)*x + log1p(e^{-x})      (clamp at -100 can never bind here)
        // two terms fused: log1p(ec)+log1p(et) = log((1+ec)(1+et))
        e = (1.0f - a) * (xc + xt) + __logf((1.0f + ec) * (1.0f + et));
    }

    // Fast path: every pc > 0 (always true unless a logit <= ~-88)
    const int allvalid = __syncthreads_and((!act) || (pc > 0.0f));

    if (allvalid) {
        // full mask, count = 199: plain sum reduction
        float v = e;
        #pragma unroll
        for (int off = 16; off > 0; off >>= 1)
            v += __shfl_xor_sync(0xFFFFFFFFu, v, off);
        if (lane == 0) shf[warp] = v;
        __syncthreads();
        if (i == 0) {
            float sum = 0.0f;
            #pragma unroll
            for (int w = 0; w < NWARP; w++) sum += shf[w];
            sh_res[0] = sum;
            sh_res[1] = (float)TM1;
        }
    } else {
        // Rare exact fallback: dynamic trim via serial scan (never hit for this data)
        sh_e[i]  = e;
        sh_pc[i] = act ? pc : 0.0f;
        __syncthreads();
        if (i == 0) {
            int last = -1;
            for (int j = 0; j < TM1; j++)
                if (sh_pc[j] > 0.0f) last = j;
            if (last < 0) last = TM1 - 1;   // argmax-of-all-false convention
            float sum = 0.0f;
            for (int j = 0; j <= last; j++) sum += sh_e[j];
            sh_res[0] = sum;
            sh_res[1] = (float)(last + 1);
        }
    }

    if (i == 0) {
        const double loss = (double)sh_res[0] / (double)sh_res[1];
        const unsigned long long fx = __double2ull_rn(loss * FXSCALE);
        atomicAdd(&g_acc, fx);                      // order-independent => deterministic
        __threadfence();
        const unsigned int ticket = atomicAdd(&g_done, 1u);
        if (ticket == BB - 1) {
            const unsigned long long total = atomicAdd(&g_acc, 0ull); // atomic read
            out[0] = (float)((double)total * (1.0 / FXSCALE));
            g_acc  = 0ull;                          // reset for next graph replay
            g_done = 0u;
        }
    }
}

extern "C" void kernel_launch(void* const* d_in, const int* in_sizes, int n_in,
                              void* d_out, int out_size)
{
    const float* logit_c = (const float*)d_in[0];
    const float* logit_t = (const float*)d_in[1];
    const int*   q_idx   = (const int*)d_in[2];
    const int*   correct = (const int*)d_in[3];
    float* out = (float*)d_out;

    fused_kernel<<<BB, NTHR>>>(logit_c, logit_t, q_idx, correct, out);
}

// round 5
// speedup vs baseline: 1.2977x; 1.2605x over previous
#include <cuda_runtime.h>
#include <math.h>

// Problem constants (fixed by the reference)
#define BB 256
#define TT 200
#define QQ 1000
#define TM1 199   // T - 1
#define NTHR 224  // 7 warps, covers 199 active lanes
#define NWARP 7

// Fixed-point: per-student loss (< 8.0) scaled by 2^40; 256 of them < 2^51.
// Completion count lives at bit 54: one atomicAdd carries both payload+ticket.
#define FXSCALE 1099511627776.0          // 2^40
#define CNT_ONE (1ull << 54)
#define SUM_MASK ((1ull << 54) - 1ull)

__device__ unsigned long long g_acc = 0ull;   // packed {count[63:54], fxsum[53:0]}

__global__ void __launch_bounds__(NTHR)
fused_kernel(const float* __restrict__ logit_c,
             const float* __restrict__ logit_t,
             const int*   __restrict__ q_idx,
             const int*   __restrict__ correct,
             float*       __restrict__ out)
{
    __shared__ float sh_wsum[NWARP];   // per-warp esum
    __shared__ int   sh_wval[NWARP];   // per-warp "all pc>0"
    __shared__ float sh_e[NTHR];       // fallback scratch
    __shared__ float sh_pc[NTHR];      // fallback scratch

    const int s    = blockIdx.x;
    const int i    = threadIdx.x;
    const int lane = i & 31;
    const int warp = i >> 5;
    const bool act = (i < TM1);

    float* __restrict__ p_mean = out + 1;
    float* __restrict__ gt     = out + 1 + (size_t)BB * TM1;

    float pc = 1.0f, e = 0.0f;
    if (act) {
        const int base = s * TT + i;            // (s, i)
        const int q    = q_idx[base + 1];       // q_idx[s, i+1]
        const float a  = (float)correct[base + 1];
        const size_t row = (size_t)base * QQ;
        const float xc = logit_c[row + q];
        const float xt = logit_t[row + q];
        const float ec = __expf(-xc);
        const float et = __expf(-xt);
        pc = __fdividef(1.0f, 1.0f + ec);
        const float pt = __fdividef(1.0f, 1.0f + et);
        const size_t o = (size_t)s * TM1 + i;
        p_mean[o] = 0.5f * (pt + pc);
        gt[o]     = a;
        // BCE(sigmoid(x),a) = (1-a)*x + log1p(e^{-x}); two steps fused into one log
        e = (1.0f - a) * (xc + xt) + __logf((1.0f + ec) * (1.0f + et));
    }

    // Stash for the rare exact-fallback path (no extra barrier needed later)
    sh_e[i]  = e;
    sh_pc[i] = act ? pc : 1.0f;

    // Per-warp sum + per-warp validity, ONE barrier total
    float v = e;
    #pragma unroll
    for (int off = 16; off > 0; off >>= 1)
        v += __shfl_xor_sync(0xFFFFFFFFu, v, off);
    const int wall = __all_sync(0xFFFFFFFFu, pc > 0.0f);
    if (lane == 0) { sh_wsum[warp] = v; sh_wval[warp] = wall; }
    __syncthreads();

    if (warp == 0) {
        float ps  = (lane < NWARP) ? sh_wsum[lane] : 0.0f;
        int   pv  = (lane < NWARP) ? sh_wval[lane] : 1;
        #pragma unroll
        for (int off = 4; off > 0; off >>= 1) {
            ps += __shfl_xor_sync(0xFFFFFFFFu, ps, off);
            pv &= __shfl_xor_sync(0xFFFFFFFFu, pv, off);
        }
        if (lane == 0) {
            float esum, cnt;
            if (pv) {                       // fast path: full mask, count = 199
                esum = ps;
                cnt  = (float)TM1;
            } else {                        // exact dynamic-trim fallback
                int last = -1;
                for (int j = 0; j < TM1; j++)
                    if (sh_pc[j] > 0.0f) last = j;
                if (last < 0) last = TM1 - 1;    // argmax-of-all-false convention
                float sum = 0.0f;
                for (int j = 0; j <= last; j++) sum += sh_e[j];
                esum = sum;
                cnt  = (float)(last + 1);
            }
            const double loss = (double)esum / (double)cnt;
            const unsigned long long fx =
                __double2ull_rn(loss * FXSCALE) + CNT_ONE;
            // Single atomic: payload + ticket. Return value of the LAST adder
            // already contains the complete total — no fence, no second atomic.
            const unsigned long long prev = atomicAdd(&g_acc, fx);
            const unsigned long long now  = prev + fx;
            if ((now >> 54) == (unsigned long long)BB) {
                out[0] = (float)((double)(now & SUM_MASK) * (1.0 / FXSCALE));
                g_acc  = 0ull;              // reset for next graph replay
            }
        }
    }
}

extern "C" void kernel_launch(void* const* d_in, const int* in_sizes, int n_in,
                              void* d_out, int out_size)
{
    const float* logit_c = (const float*)d_in[0];
    const float* logit_t = (const float*)d_in[1];
    const int*   q_idx   = (const int*)d_in[2];
    const int*   correct = (const int*)d_in[3];
    float* out = (float*)d_out;

    fused_kernel<<<BB, NTHR>>>(logit_c, logit_t, q_idx, correct, out);
}

// round 6
// speedup vs baseline: 1.3413x; 1.0337x over previous
#include <cuda_runtime.h>
#include <math.h>

// Problem constants (fixed by the reference)
#define BB 256
#define TT 200
#define QQ 1000
#define TM1 199    // T - 1
#define NTHR 64    // 2 warps; each thread covers 4 strided steps
#define KPT 4      // steps per thread (stride NTHR)

// Fixed-point: per-student loss (< 8.0) scaled by 2^40; 256 of them < 2^51.
// Completion count lives at bit 54: one atomicAdd carries payload + ticket.
#define FXSCALE 1099511627776.0          // 2^40
#define CNT_ONE (1ull << 54)
#define SUM_MASK ((1ull << 54) - 1ull)

__device__ unsigned long long g_acc = 0ull;   // packed {count[63:54], fxsum[53:0]}

__global__ void __launch_bounds__(NTHR)
fused_kernel(const float* __restrict__ logit_c,
             const float* __restrict__ logit_t,
             const int*   __restrict__ q_idx,
             const int*   __restrict__ correct,
             float*       __restrict__ out)
{
    __shared__ float sh_wsum[2];
    __shared__ int   sh_wval[2];
    __shared__ float sh_e[TM1 + 1];    // fallback only
    __shared__ float sh_pc[TM1 + 1];   // fallback only

    const int s    = blockIdx.x;
    const int i    = threadIdx.x;
    const int lane = i & 31;
    const int warp = i >> 5;

    float* __restrict__ p_mean = out + 1;
    float* __restrict__ gt     = out + 1 + (size_t)BB * TM1;

    // ---- Pass 1: batched index/label loads (coalesced) ----
    int   qv[KPT];
    float av[KPT];
    bool  actv[KPT];
    #pragma unroll
    for (int k = 0; k < KPT; k++) {
        const int idx = i + k * NTHR;
        actv[k] = (idx < TM1);
        const int base = s * TT + idx + 1;
        qv[k] = actv[k] ? q_idx[base]   : 0;
        av[k] = actv[k] ? (float)correct[base] : 0.0f;
    }

    // ---- Pass 2: batched logit gathers (8 independent LDGs in flight) ----
    float xcv[KPT], xtv[KPT];
    #pragma unroll
    for (int k = 0; k < KPT; k++) {
        if (actv[k]) {
            const int idx = i + k * NTHR;
            const size_t row = (size_t)(s * TT + idx) * QQ + qv[k];
            xcv[k] = logit_c[row];
            xtv[k] = logit_t[row];
        } else { xcv[k] = 0.0f; xtv[k] = 0.0f; }
    }

    // ---- Pass 3: compute + elementwise outputs ----
    float ev[KPT], pcv[KPT];
    float e_acc = 0.0f;
    bool  allpos = true;
    #pragma unroll
    for (int k = 0; k < KPT; k++) {
        if (actv[k]) {
            const float ec = __expf(-xcv[k]);
            const float et = __expf(-xtv[k]);
            const float pc = __fdividef(1.0f, 1.0f + ec);
            const float pt = __fdividef(1.0f, 1.0f + et);
            const int idx = i + k * NTHR;
            const size_t o = (size_t)s * TM1 + idx;
            p_mean[o] = 0.5f * (pt + pc);
            gt[o]     = av[k];
            // BCE(sigmoid(x),a) = (1-a)*x + log1p(e^{-x}); both terms in one log
            const float e = (1.0f - av[k]) * (xcv[k] + xtv[k])
                          + __logf((1.0f + ec) * (1.0f + et));
            ev[k] = e; pcv[k] = pc;
            e_acc += e;
            allpos = allpos && (pc > 0.0f);
        } else { ev[k] = 0.0f; pcv[k] = 1.0f; }
    }

    // ---- Reduce: per-warp sum + validity, ONE barrier on fast path ----
    float v = e_acc;
    #pragma unroll
    for (int off = 16; off > 0; off >>= 1)
        v += __shfl_xor_sync(0xFFFFFFFFu, v, off);
    const int wall = __all_sync(0xFFFFFFFFu, allpos);
    if (lane == 0) { sh_wsum[warp] = v; sh_wval[warp] = wall; }
    __syncthreads();

    if (sh_wval[0] & sh_wval[1]) {
        // Fast path: full mask, count = 199
        if (i == 0) {
            const float esum = sh_wsum[0] + sh_wsum[1];
            const double loss = (double)esum * (1.0 / (double)TM1);
            const unsigned long long fx =
                __double2ull_rn(loss * FXSCALE) + CNT_ONE;
            const unsigned long long now = atomicAdd(&g_acc, fx) + fx;
            if ((now >> 54) == (unsigned long long)BB) {
                out[0] = (float)((double)(now & SUM_MASK) * (1.0 / FXSCALE));
                g_acc  = 0ull;              // reset for next graph replay
            }
        }
    } else {
        // Rare exact dynamic-trim fallback
        #pragma unroll
        for (int k = 0; k < KPT; k++) {
            const int idx = i + k * NTHR;
            if (actv[k]) { sh_e[idx] = ev[k]; sh_pc[idx] = pcv[k]; }
        }
        __syncthreads();
        if (i == 0) {
            int last = -1;
            for (int j = 0; j < TM1; j++)
                if (sh_pc[j] > 0.0f) last = j;
            if (last < 0) last = TM1 - 1;   // argmax-of-all-false convention
            float sum = 0.0f;
            for (int j = 0; j <= last; j++) sum += sh_e[j];
            const double loss = (double)sum / (double)(last + 1);
            const unsigned long long fx =
                __double2ull_rn(loss * FXSCALE) + CNT_ONE;
            const unsigned long long now = atomicAdd(&g_acc, fx) + fx;
            if ((now >> 54) == (unsigned long long)BB) {
                out[0] = (float)((double)(now & SUM_MASK) * (1.0 / FXSCALE));
                g_acc  = 0ull;
            }
        }
    }
}

extern "C" void kernel_launch(void* const* d_in, const int* in_sizes, int n_in,
                              void* d_out, int out_size)
{
    const float* logit_c = (const float*)d_in[0];
    const float* logit_t = (const float*)d_in[1];
    const int*   q_idx   = (const int*)d_in[2];
    const int*   correct = (const int*)d_in[3];
    float* out = (float*)d_out;

    fused_kernel<<<BB, NTHR>>>(logit_c, logit_t, q_idx, correct, out);
}